// round 3
// baseline (speedup 1.0000x reference)
#include <cuda_runtime.h>

#define NN 12288
#define EE 393216
#define INDIM 256
#define HID 64

// ---------------- small scratch only (lazy-load alloc stays tiny) ------------
__device__ int   g_deg[NN];
__device__ float g_dinv[NN];
__device__ float g_c[NN];
__device__ float g_aggc[NN];
__device__ float g_hs[NN * HID];   // must survive into SYRK (reads while s_ is written)

// ---------------- degree / dinv ----------------------------------------------
__global__ void k_zero_deg() {
    int i = blockIdx.x * blockDim.x + threadIdx.x;
    if (i < NN) g_deg[i] = 0;
}
__global__ void k_count(const int* __restrict__ ei) {
    int e = blockIdx.x * blockDim.x + threadIdx.x;
    if (e < EE) atomicAdd(&g_deg[ei[EE + e]], 1);
}
__global__ void k_dinv() {
    int i = blockIdx.x * blockDim.x + threadIdx.x;
    if (i < NN) g_dinv[i] = rsqrtf((float)g_deg[i] + 1.0f);   // +1 self-loop
}

// ---------------- aggregation: self-loop init + edge-parallel atomic scatter -
__global__ void k_init64(const float* __restrict__ in, float* __restrict__ out) {
    int idx = blockIdx.x * blockDim.x + threadIdx.x;
    if (idx >= NN * 64) return;
    int i = idx >> 6;
    float w = g_dinv[i];
    out[idx] = w * w * in[idx];
}
__global__ void k_init32(const float* __restrict__ z, int off, float* __restrict__ out) {
    int idx = blockIdx.x * blockDim.x + threadIdx.x;
    if (idx >= NN * 32) return;
    int i = idx >> 5, l = idx & 31;
    float w = g_dinv[i];
    out[idx] = w * w * z[i * 64 + off + l];
}
__global__ void k_scat64(const float* __restrict__ in, float* __restrict__ out,
                         const int* __restrict__ ei) {
    int e = (blockIdx.x * 256 + threadIdx.x) >> 5;
    int lane = threadIdx.x & 31;
    if (e >= EE) return;
    int s = ei[e], d = ei[EE + e];
    float nrm = g_dinv[s] * g_dinv[d];
    const float* p = in + s * 64;
    atomicAdd(&out[d * 64 + lane], nrm * p[lane]);
    atomicAdd(&out[d * 64 + 32 + lane], nrm * p[32 + lane]);
}
__global__ void k_scat32(const float* __restrict__ z, int off, float* __restrict__ out,
                         const int* __restrict__ ei) {
    int e = (blockIdx.x * 256 + threadIdx.x) >> 5;
    int lane = threadIdx.x & 31;
    if (e >= EE) return;
    int s = ei[e], d = ei[EE + e];
    float nrm = g_dinv[s] * g_dinv[d];
    atomicAdd(&out[d * 32 + lane], nrm * z[s * 64 + off + lane]);
}

// scalar aggregation of c (rank-1 counterfactual path)
__global__ void k_initS() {
    int i = blockIdx.x * blockDim.x + threadIdx.x;
    if (i < NN) { float w = g_dinv[i]; g_aggc[i] = w * w * g_c[i]; }
}
__global__ void k_scatS(const int* __restrict__ ei) {
    int e = blockIdx.x * blockDim.x + threadIdx.x;
    if (e >= EE) return;
    int s = ei[e], d = ei[EE + e];
    atomicAdd(&g_aggc[d], g_dinv[s] * g_dinv[d] * g_c[s]);
}

// ---------------- dead-simple GEMM: out[N,KOUT] = A[N,KIN]@W[KIN,KOUT] (+b) --
template <int KIN, int KOUT, bool RELU>
__global__ void k_gemm(const float* __restrict__ A, const float* __restrict__ W,
                       const float* __restrict__ b, float* __restrict__ out) {
    int idx = blockIdx.x * blockDim.x + threadIdx.x;
    if (idx >= NN * KOUT) return;
    int row = idx / KOUT, c = idx % KOUT;
    float acc = b ? b[c] : 0.f;
    const float* a = A + row * KIN;
#pragma unroll 8
    for (int k = 0; k < KIN; k++) acc += a[k] * W[k * KOUT + c];
    if (RELU) acc = fmaxf(acc, 0.f);
    out[idx] = acc;
}

// ---------------- misc elementwise -------------------------------------------
__global__ void k_cvec(const float* __restrict__ x) {
    int i = blockIdx.x * blockDim.x + threadIdx.x;
    if (i < NN) g_c[i] = 1.0f - 2.0f * x[i * INDIM];
}
// h1 = relu(A1 + b1); h1cf = relu(A1 + aggc*W1[0,:] + b1)
__global__ void k_h1(const float* __restrict__ A1, const float* __restrict__ W1,
                     const float* __restrict__ b1, float* __restrict__ h1,
                     float* __restrict__ h1cf) {
    int idx = blockIdx.x * blockDim.x + threadIdx.x;
    if (idx >= NN * HID) return;
    int i = idx >> 6, l = idx & 63;
    float base = A1[idx] + b1[l];
    h1[idx] = fmaxf(base, 0.f);
    h1cf[idx] = fmaxf(base + g_aggc[i] * W1[l], 0.f);   // W1 row 0 = first 64 floats
}
__global__ void k_split(const float* __restrict__ z, float* __restrict__ ozs,
                        float* __restrict__ ozns) {
    int idx = blockIdx.x * blockDim.x + threadIdx.x;
    if (idx >= NN * 32) return;
    int i = idx >> 5, l = idx & 31;
    ozs[idx] = z[i * 64 + l];
    ozns[idx] = z[i * 64 + 32 + l];
}

// ---------------- SYRK: C = hs @ hs^T (upper blocks + mirrored stores) -------
__global__ void k_syrk(const float* __restrict__ hs, float* __restrict__ C) {
    int bi = blockIdx.y, bj = blockIdx.x;
    if (bj < bi) return;
    __shared__ float sA[64 * 65];
    __shared__ float sB[64 * 65];
    int tid = threadIdx.x;
    for (int i = tid; i < 64 * 64; i += 256) {
        int r = i >> 6, k = i & 63;
        sA[k * 65 + r] = hs[(bi * 64 + r) * 64 + k];
        sB[k * 65 + r] = hs[(bj * 64 + r) * 64 + k];
    }
    __syncthreads();
    int tx = tid & 15, ty = tid >> 4;
    float acc[4][4] = {};
    for (int k = 0; k < 64; k++) {
        float a[4], b[4];
#pragma unroll
        for (int i = 0; i < 4; i++) {
            a[i] = sA[k * 65 + ty + 16 * i];
            b[i] = sB[k * 65 + tx + 16 * i];
        }
#pragma unroll
        for (int i = 0; i < 4; i++)
#pragma unroll
            for (int j = 0; j < 4; j++) acc[i][j] += a[i] * b[j];
    }
#pragma unroll
    for (int i = 0; i < 4; i++) {
        int row = bi * 64 + ty + 16 * i;
#pragma unroll
        for (int j = 0; j < 4; j++)
            C[(size_t)row * NN + bj * 64 + tx + 16 * j] = acc[i][j];
    }
    if (bi != bj) {
        __syncthreads();
#pragma unroll
        for (int i = 0; i < 4; i++)
#pragma unroll
            for (int j = 0; j < 4; j++)
                sA[(tx + 16 * j) * 65 + (ty + 16 * i)] = acc[i][j];
        __syncthreads();
        for (int idx = tid; idx < 4096; idx += 256) {
            int r2 = idx >> 6, c2 = idx & 63;
            C[(size_t)(bj * 64 + r2) * NN + bi * 64 + c2] = sA[r2 * 65 + c2];
        }
    }
}

// ---------------- input-order hypotheses --------------------------------------
// logical: 0:x 1:ei 2:enc_W1 3:enc_b1 4:enc_W2 5:enc_b2 6:d1_W1 7:d1_b1
//          8:d1_W2 9:d1_b2 10:d2_W1 11:d2_b1 12:d2_W2 13:d2_b2 14:s_W 15:s_b
static const int SIGS[6][16] = {
  {3145728,786432,16384,64,4096,64,2048,64,16384,256,2048,64,16384,256,2048,64},   // dict
  {2048,16384,64,256,2048,16384,64,256,786432,16384,4096,64,64,2048,64,3145728},   // ASCII alpha
  {64,256,2048,16384,64,256,2048,16384,786432,64,64,16384,4096,64,2048,3145728},   // CI alpha
  {64,2048,256,16384,64,2048,256,16384,64,2048,64,4096,64,16384,786432,3145728},   // reverse dict
  {3145728,786432,16384,16384,16384,4096,2048,2048,2048,256,256,64,64,64,64,64},   // size desc
  {64,64,64,64,64,256,256,2048,2048,2048,4096,16384,16384,16384,786432,3145728},   // size asc
};
static const int MAPS[6][16] = {
  {0,1,2,3,4,5,6,7,8,9,10,11,12,13,14,15},
  {15,8,9,11,10,12,0,2,1,3,4,6,5,7,13,14},
  {15,8,11,9,12,10,2,0,3,1,6,4,7,5,14,13},
  {15,14,13,12,11,10,9,8,7,6,5,4,3,2,1,0},
  {0,1,2,11,5,12,6,13,3,9,7,14,4,10,8,15},
  {15,14,11,0,10,1,7,2,12,5,8,3,13,6,9,4},
};

// ---------------- launch ------------------------------------------------------
extern "C" void kernel_launch(void* const* d_in, const int* in_sizes, int n_in,
                              void* d_out, int out_size) {
    const int* map = MAPS[0];
    for (int h = 0; h < 6; h++) {
        bool ok = (n_in >= 16);
        for (int i = 0; ok && i < 16; i++) ok = (in_sizes[i] == SIGS[h][i]);
        if (ok) { map = MAPS[h]; break; }
    }
    const float* x      = (const float*)d_in[map[0]];
    const int*   ei     = (const int*)  d_in[map[1]];
    const float* enc_W1 = (const float*)d_in[map[2]];
    const float* enc_b1 = (const float*)d_in[map[3]];
    const float* enc_W2 = (const float*)d_in[map[4]];
    const float* enc_b2 = (const float*)d_in[map[5]];
    const float* d1_W1  = (const float*)d_in[map[6]];
    const float* d1_b1  = (const float*)d_in[map[7]];
    const float* d1_W2  = (const float*)d_in[map[8]];
    const float* d1_b2  = (const float*)d_in[map[9]];
    const float* d2_W1  = (const float*)d_in[map[10]];
    const float* d2_b1  = (const float*)d_in[map[11]];
    const float* d2_W2  = (const float*)d_in[map[12]];
    const float* d2_b2  = (const float*)d_in[map[13]];
    const float* s_W    = (const float*)d_in[map[14]];
    const float* s_b    = (const float*)d_in[map[15]];
    float* out = (float*)d_out;

    // outputs (tuple order, row-major each)
    float* o_zs   = out;                       // [N,32]
    float* o_zns  = out + (size_t)NN * 32;     // [N,32]
    float* o_xs   = out + (size_t)NN * 64;     // [N,256]
    float* o_xns  = o_xs + (size_t)NN * 256;   // [N,256]
    float* o_xscf = o_xns + (size_t)NN * 256;  // [N,256]
    float* o_s    = o_xscf + (size_t)NN * 256; // [N,N]  (written LAST)

    // large scratch carved out of the s_ region (SYRK overwrites it at the end)
    const size_t CH = (size_t)NN * 64;   // 786432 floats per chunk
    float* sc_y1   = o_s + 0 * CH;
    float* sc_A1   = o_s + 1 * CH;
    float* sc_h1   = o_s + 2 * CH;
    float* sc_h1cf = o_s + 3 * CH;
    float* sc_B    = o_s + 4 * CH;
    float* sc_Bcf  = o_s + 5 * CH;
    float* sc_z    = o_s + 6 * CH;
    float* sc_zcf  = o_s + 7 * CH;
    float* sc_t    = o_s + 8 * CH;
    float* sc_at   = o_s + 9 * CH;
    float* sc_az   = o_s + 10 * CH;                    // [N,32]
    float* sc_az2  = o_s + 10 * CH + (size_t)NN * 32;  // [N,32]

    const int TB = 256;
    const int gN   = (NN + TB - 1) / TB;
    const int gE   = (EE + TB - 1) / TB;
    const int gN64 = (NN * 64 + TB - 1) / TB;
    const int gN32 = (NN * 32 + TB - 1) / TB;
    const int gN256 = (NN * 256 + TB - 1) / TB;
    const int gEW  = (EE * 32 + TB - 1) / TB;

    // degrees -> dinv
    k_zero_deg<<<gN, TB>>>();
    k_count<<<gE, TB>>>(ei);
    k_dinv<<<gN, TB>>>();

    // encoder conv1: y1 = x@W1 ; A1 = agg(y1) ; rank-1 counterfactual path
    k_gemm<INDIM, 64, false><<<gN64, TB>>>(x, enc_W1, nullptr, sc_y1);
    k_cvec<<<gN, TB>>>(x);
    k_init64<<<gN64, TB>>>(sc_y1, sc_A1);
    k_scat64<<<gEW, TB>>>(sc_y1, sc_A1, ei);
    k_initS<<<gN, TB>>>();
    k_scatS<<<gE, TB>>>(ei);
    k_h1<<<gN64, TB>>>(sc_A1, enc_W1, enc_b1, sc_h1, sc_h1cf);

    // encoder conv2 (agg then matmul; segment_sum is linear so this is exact)
    k_init64<<<gN64, TB>>>(sc_h1, sc_B);
    k_scat64<<<gEW, TB>>>(sc_h1, sc_B, ei);
    k_init64<<<gN64, TB>>>(sc_h1cf, sc_Bcf);
    k_scat64<<<gEW, TB>>>(sc_h1cf, sc_Bcf, ei);
    k_gemm<64, 64, false><<<gN64, TB>>>(sc_B, enc_W2, enc_b2, sc_z);
    k_gemm<64, 64, false><<<gN64, TB>>>(sc_Bcf, enc_W2, enc_b2, sc_zcf);
    k_split<<<gN32, TB>>>(sc_z, o_zs, o_zns);

    // dec1(z_s)
    k_init32<<<gN32, TB>>>(sc_z, 0, sc_az);
    k_scat32<<<gEW, TB>>>(sc_z, 0, sc_az, ei);
    k_gemm<32, 64, true><<<gN64, TB>>>(sc_az, d1_W1, d1_b1, sc_t);
    k_init64<<<gN64, TB>>>(sc_t, sc_at);
    k_scat64<<<gEW, TB>>>(sc_t, sc_at, ei);
    k_gemm<64, 256, false><<<gN256, TB>>>(sc_at, d1_W2, d1_b2, o_xs);

    // dec2(z_ns)  (agg(z_ns) kept for hs)
    k_init32<<<gN32, TB>>>(sc_z, 32, sc_az2);
    k_scat32<<<gEW, TB>>>(sc_z, 32, sc_az2, ei);
    k_gemm<32, 64, false><<<gN64, TB>>>(sc_az2, s_W, s_b, g_hs);   // hs first (az2 reused)
    k_gemm<32, 64, true><<<gN64, TB>>>(sc_az2, d2_W1, d2_b1, sc_t);
    k_init64<<<gN64, TB>>>(sc_t, sc_at);
    k_scat64<<<gEW, TB>>>(sc_t, sc_at, ei);
    k_gemm<64, 256, false><<<gN256, TB>>>(sc_at, d2_W2, d2_b2, o_xns);

    // dec1(z_s_cf)
    k_init32<<<gN32, TB>>>(sc_zcf, 0, sc_az);
    k_scat32<<<gEW, TB>>>(sc_zcf, 0, sc_az, ei);
    k_gemm<32, 64, true><<<gN64, TB>>>(sc_az, d1_W1, d1_b1, sc_t);
    k_init64<<<gN64, TB>>>(sc_t, sc_at);
    k_scat64<<<gEW, TB>>>(sc_t, sc_at, ei);
    k_gemm<64, 256, false><<<gN256, TB>>>(sc_at, d1_W2, d1_b2, o_xscf);

    // s_ = hs @ hs^T  — overwrites the entire scratch region last
    dim3 syrk_grid(NN / 64, NN / 64);
    k_syrk<<<syrk_grid, TB>>>(g_hs, o_s);
}

// round 4
// speedup vs baseline: 1.3899x; 1.3899x over previous
#include <cuda_runtime.h>

#define NN 12288
#define EE 393216
#define INDIM 256
#define HID 64

// ---------------- small static scratch (CSR + tiny vectors + hs) -------------
__device__ int   g_deg[NN];
__device__ float g_dinv[NN];
__device__ int   g_rowptr[NN + 1];
__device__ int   g_cursor[NN];
__device__ int   g_col[EE];
__device__ float g_val[EE];
__device__ float g_c[NN];
__device__ float g_aggc[NN];
__device__ float g_hs[NN * HID];   // read by SYRK while s_ region is overwritten

// ---------------- CSR build ---------------------------------------------------
__global__ void k_zero_deg() {
    int i = blockIdx.x * blockDim.x + threadIdx.x;
    if (i < NN) g_deg[i] = 0;
}
__global__ void k_count(const int* __restrict__ ei) {
    int e = blockIdx.x * blockDim.x + threadIdx.x;
    if (e < EE) atomicAdd(&g_deg[ei[EE + e]], 1);
}
__global__ void k_dinv() {
    int i = blockIdx.x * blockDim.x + threadIdx.x;
    if (i < NN) g_dinv[i] = rsqrtf((float)g_deg[i] + 1.0f);   // +1 self-loop
}
// single-block exclusive scan over NN = 1024*12 degrees
__global__ void k_scan() {
    __shared__ int ssum[1024];
    int t = threadIdx.x;
    int base = t * 12;
    int loc[12];
    int s = 0;
#pragma unroll
    for (int i = 0; i < 12; i++) { loc[i] = s; s += g_deg[base + i]; }
    ssum[t] = s;
    __syncthreads();
    if (t == 0) {
        int acc = 0;
        for (int i = 0; i < 1024; i++) { int v = ssum[i]; ssum[i] = acc; acc += v; }
    }
    __syncthreads();
    int off = ssum[t];
#pragma unroll
    for (int i = 0; i < 12; i++) {
        g_rowptr[base + i] = off + loc[i];
        g_cursor[base + i] = off + loc[i];
    }
    if (t == 1023) g_rowptr[NN] = off + s;
}
__global__ void k_scatter(const int* __restrict__ ei) {
    int e = blockIdx.x * blockDim.x + threadIdx.x;
    if (e >= EE) return;
    int s = ei[e], d = ei[EE + e];
    int p = atomicAdd(&g_cursor[d], 1);
    g_col[p] = s;
    g_val[p] = g_dinv[s] * g_dinv[d];
}

// ---------------- deterministic CSR gather aggregations -----------------------
// one warp per node; 64 dims -> 2 floats/lane; self-loop inline
__global__ void k_agg64(const float* __restrict__ in, float* __restrict__ out) {
    int w = (blockIdx.x * 256 + threadIdx.x) >> 5;
    int lane = threadIdx.x & 31;
    if (w >= NN) return;
    int s0 = g_rowptr[w], s1 = g_rowptr[w + 1];
    float a0 = 0.f, a1 = 0.f;
    for (int j = s0; j < s1; j++) {
        int s = g_col[j];
        float wt = g_val[j];
        const float* p = in + s * 64;
        a0 += wt * p[lane];
        a1 += wt * p[32 + lane];
    }
    float ws = g_dinv[w] * g_dinv[w];
    const float* p = in + w * 64;
    a0 += ws * p[lane];
    a1 += ws * p[32 + lane];
    out[w * 64 + lane] = a0;
    out[w * 64 + 32 + lane] = a1;
}

// two 64-dim inputs, one CSR traversal
__global__ void k_agg64x2(const float* __restrict__ in1, const float* __restrict__ in2,
                          float* __restrict__ out1, float* __restrict__ out2) {
    int w = (blockIdx.x * 256 + threadIdx.x) >> 5;
    int lane = threadIdx.x & 31;
    if (w >= NN) return;
    int s0 = g_rowptr[w], s1 = g_rowptr[w + 1];
    float a0 = 0.f, a1 = 0.f, b0 = 0.f, b1 = 0.f;
    for (int j = s0; j < s1; j++) {
        int s = g_col[j];
        float wt = g_val[j];
        const float* p1 = in1 + s * 64;
        const float* p2 = in2 + s * 64;
        a0 += wt * p1[lane];  a1 += wt * p1[32 + lane];
        b0 += wt * p2[lane];  b1 += wt * p2[32 + lane];
    }
    float ws = g_dinv[w] * g_dinv[w];
    const float* p1 = in1 + w * 64;
    const float* p2 = in2 + w * 64;
    a0 += ws * p1[lane];  a1 += ws * p1[32 + lane];
    b0 += ws * p2[lane];  b1 += ws * p2[32 + lane];
    out1[w * 64 + lane] = a0;  out1[w * 64 + 32 + lane] = a1;
    out2[w * 64 + lane] = b0;  out2[w * 64 + 32 + lane] = b1;
}

// three 64-dim inputs, one CSR traversal (decoder t's)
__global__ void k_agg64x3(const float* __restrict__ in1, const float* __restrict__ in2,
                          const float* __restrict__ in3, float* __restrict__ out1,
                          float* __restrict__ out2, float* __restrict__ out3) {
    int w = (blockIdx.x * 256 + threadIdx.x) >> 5;
    int lane = threadIdx.x & 31;
    if (w >= NN) return;
    int s0 = g_rowptr[w], s1 = g_rowptr[w + 1];
    float a0 = 0.f, a1 = 0.f, b0 = 0.f, b1 = 0.f, c0 = 0.f, c1 = 0.f;
    for (int j = s0; j < s1; j++) {
        int s = g_col[j];
        float wt = g_val[j];
        const float* p1 = in1 + s * 64;
        const float* p2 = in2 + s * 64;
        const float* p3 = in3 + s * 64;
        a0 += wt * p1[lane];  a1 += wt * p1[32 + lane];
        b0 += wt * p2[lane];  b1 += wt * p2[32 + lane];
        c0 += wt * p3[lane];  c1 += wt * p3[32 + lane];
    }
    float ws = g_dinv[w] * g_dinv[w];
    const float* p1 = in1 + w * 64;
    const float* p2 = in2 + w * 64;
    const float* p3 = in3 + w * 64;
    a0 += ws * p1[lane];  a1 += ws * p1[32 + lane];
    b0 += ws * p2[lane];  b1 += ws * p2[32 + lane];
    c0 += ws * p3[lane];  c1 += ws * p3[32 + lane];
    out1[w * 64 + lane] = a0;  out1[w * 64 + 32 + lane] = a1;
    out2[w * 64 + lane] = b0;  out2[w * 64 + 32 + lane] = b1;
    out3[w * 64 + lane] = c0;  out3[w * 64 + 32 + lane] = c1;
}

// z_s / z_ns / z_s_cf aggregation in one pass: az  = agg(z[:, 0:32]),
// az2 = agg(z[:,32:64]), azcf = agg(zcf[:, 0:32])
__global__ void k_agg96(const float* __restrict__ z, const float* __restrict__ zcf,
                        float* __restrict__ az, float* __restrict__ az2,
                        float* __restrict__ azcf) {
    int w = (blockIdx.x * 256 + threadIdx.x) >> 5;
    int lane = threadIdx.x & 31;
    if (w >= NN) return;
    int s0 = g_rowptr[w], s1 = g_rowptr[w + 1];
    float a0 = 0.f, a1 = 0.f, c0 = 0.f;
    for (int j = s0; j < s1; j++) {
        int s = g_col[j];
        float wt = g_val[j];
        const float* pz = z + s * 64;
        a0 += wt * pz[lane];
        a1 += wt * pz[32 + lane];
        c0 += wt * zcf[s * 64 + lane];
    }
    float ws = g_dinv[w] * g_dinv[w];
    const float* pz = z + w * 64;
    a0 += ws * pz[lane];
    a1 += ws * pz[32 + lane];
    c0 += ws * zcf[w * 64 + lane];
    az[w * 32 + lane] = a0;
    az2[w * 32 + lane] = a1;
    azcf[w * 32 + lane] = c0;
}

// scalar aggregation of c (rank-1 counterfactual path)
__global__ void k_aggscalar() {
    int w = (blockIdx.x * 256 + threadIdx.x) >> 5;
    int lane = threadIdx.x & 31;
    if (w >= NN) return;
    int s0 = g_rowptr[w], s1 = g_rowptr[w + 1];
    float a = 0.f;
    for (int j = s0 + lane; j < s1; j += 32)
        a += g_val[j] * g_c[g_col[j]];
#pragma unroll
    for (int o = 16; o; o >>= 1) a += __shfl_xor_sync(0xffffffffu, a, o);
    if (lane == 0) {
        float ws = g_dinv[w] * g_dinv[w];
        g_aggc[w] = a + ws * g_c[w];
    }
}

// ---------------- GEMM: out[N,KOUT] = A[N,KIN]@W[KIN,KOUT] (+b)(+relu) -------
// 4 outputs per thread via float4 W loads
template <int KIN, int KOUT, bool RELU>
__global__ void k_gemm4(const float* __restrict__ A, const float* __restrict__ W,
                        const float* __restrict__ b, float* __restrict__ out) {
    constexpr int C4 = KOUT / 4;
    int idx = blockIdx.x * blockDim.x + threadIdx.x;
    if (idx >= NN * C4) return;
    int row = idx / C4, c4 = (idx % C4) * 4;
    float4 acc;
    if (b) { acc.x = b[c4]; acc.y = b[c4 + 1]; acc.z = b[c4 + 2]; acc.w = b[c4 + 3]; }
    else   { acc.x = acc.y = acc.z = acc.w = 0.f; }
    const float* a = A + row * KIN;
#pragma unroll 8
    for (int k = 0; k < KIN; k++) {
        float av = a[k];
        float4 w4 = *reinterpret_cast<const float4*>(&W[k * KOUT + c4]);
        acc.x += av * w4.x; acc.y += av * w4.y;
        acc.z += av * w4.z; acc.w += av * w4.w;
    }
    if (RELU) {
        acc.x = fmaxf(acc.x, 0.f); acc.y = fmaxf(acc.y, 0.f);
        acc.z = fmaxf(acc.z, 0.f); acc.w = fmaxf(acc.w, 0.f);
    }
    *reinterpret_cast<float4*>(&out[row * KOUT + c4]) = acc;
}

// ---------------- misc elementwise -------------------------------------------
__global__ void k_cvec(const float* __restrict__ x) {
    int i = blockIdx.x * blockDim.x + threadIdx.x;
    if (i < NN) g_c[i] = 1.0f - 2.0f * x[i * INDIM];
}
// h1 = relu(A1 + b1); h1cf = relu(A1 + aggc*W1[0,:] + b1)
__global__ void k_h1(const float* __restrict__ A1, const float* __restrict__ W1,
                     const float* __restrict__ b1, float* __restrict__ h1,
                     float* __restrict__ h1cf) {
    int idx = blockIdx.x * blockDim.x + threadIdx.x;
    if (idx >= NN * HID) return;
    int i = idx >> 6, l = idx & 63;
    float base = A1[idx] + b1[l];
    h1[idx] = fmaxf(base, 0.f);
    h1cf[idx] = fmaxf(base + g_aggc[i] * W1[l], 0.f);   // W1 row 0 = first 64 floats
}
__global__ void k_split(const float* __restrict__ z, float* __restrict__ ozs,
                        float* __restrict__ ozns) {
    int idx = blockIdx.x * blockDim.x + threadIdx.x;
    if (idx >= NN * 32) return;
    int i = idx >> 5, l = idx & 31;
    ozs[idx] = z[i * 64 + l];
    ozns[idx] = z[i * 64 + 32 + l];
}

// ---------------- SYRK: C = hs @ hs^T (upper blocks + mirrored stores) -------
__global__ void k_syrk(const float* __restrict__ hs, float* __restrict__ C) {
    int bi = blockIdx.y, bj = blockIdx.x;
    if (bj < bi) return;
    __shared__ float sA[64 * 65];
    __shared__ float sB[64 * 65];
    int tid = threadIdx.x;
    for (int i = tid; i < 64 * 64; i += 256) {
        int r = i >> 6, k = i & 63;
        sA[k * 65 + r] = hs[(bi * 64 + r) * 64 + k];
        sB[k * 65 + r] = hs[(bj * 64 + r) * 64 + k];
    }
    __syncthreads();
    int tx = tid & 15, ty = tid >> 4;
    float acc[4][4] = {};
    for (int k = 0; k < 64; k++) {
        float a[4], b[4];
#pragma unroll
        for (int i = 0; i < 4; i++) {
            a[i] = sA[k * 65 + ty + 16 * i];
            b[i] = sB[k * 65 + tx + 16 * i];
        }
#pragma unroll
        for (int i = 0; i < 4; i++)
#pragma unroll
            for (int j = 0; j < 4; j++) acc[i][j] += a[i] * b[j];
    }
#pragma unroll
    for (int i = 0; i < 4; i++) {
        int row = bi * 64 + ty + 16 * i;
#pragma unroll
        for (int j = 0; j < 4; j++)
            C[(size_t)row * NN + bj * 64 + tx + 16 * j] = acc[i][j];
    }
    if (bi != bj) {
        __syncthreads();
#pragma unroll
        for (int i = 0; i < 4; i++)
#pragma unroll
            for (int j = 0; j < 4; j++)
                sA[(tx + 16 * j) * 65 + (ty + 16 * i)] = acc[i][j];
        __syncthreads();
        for (int idx = tid; idx < 4096; idx += 256) {
            int r2 = idx >> 6, c2 = idx & 63;
            C[(size_t)(bj * 64 + r2) * NN + bi * 64 + c2] = sA[r2 * 65 + c2];
        }
    }
}

// ---------------- input-order hypotheses (round-3 validated) ------------------
static const int SIGS[6][16] = {
  {3145728,786432,16384,64,4096,64,2048,64,16384,256,2048,64,16384,256,2048,64},   // dict
  {2048,16384,64,256,2048,16384,64,256,786432,16384,4096,64,64,2048,64,3145728},   // ASCII alpha
  {64,256,2048,16384,64,256,2048,16384,786432,64,64,16384,4096,64,2048,3145728},   // CI alpha
  {64,2048,256,16384,64,2048,256,16384,64,2048,64,4096,64,16384,786432,3145728},   // reverse dict
  {3145728,786432,16384,16384,16384,4096,2048,2048,2048,256,256,64,64,64,64,64},   // size desc
  {64,64,64,64,64,256,256,2048,2048,2048,4096,16384,16384,16384,786432,3145728},   // size asc
};
static const int MAPS[6][16] = {
  {0,1,2,3,4,5,6,7,8,9,10,11,12,13,14,15},
  {15,8,9,11,10,12,0,2,1,3,4,6,5,7,13,14},
  {15,8,11,9,12,10,2,0,3,1,6,4,7,5,14,13},
  {15,14,13,12,11,10,9,8,7,6,5,4,3,2,1,0},
  {0,1,2,11,5,12,6,13,3,9,7,14,4,10,8,15},
  {15,14,11,0,10,1,7,2,12,5,8,3,13,6,9,4},
};

// ---------------- launch ------------------------------------------------------
extern "C" void kernel_launch(void* const* d_in, const int* in_sizes, int n_in,
                              void* d_out, int out_size) {
    const int* map = MAPS[0];
    for (int h = 0; h < 6; h++) {
        bool ok = (n_in >= 16);
        for (int i = 0; ok && i < 16; i++) ok = (in_sizes[i] == SIGS[h][i]);
        if (ok) { map = MAPS[h]; break; }
    }
    const float* x      = (const float*)d_in[map[0]];
    const int*   ei     = (const int*)  d_in[map[1]];
    const float* enc_W1 = (const float*)d_in[map[2]];
    const float* enc_b1 = (const float*)d_in[map[3]];
    const float* enc_W2 = (const float*)d_in[map[4]];
    const float* enc_b2 = (const float*)d_in[map[5]];
    const float* d1_W1  = (const float*)d_in[map[6]];
    const float* d1_b1  = (const float*)d_in[map[7]];
    const float* d1_W2  = (const float*)d_in[map[8]];
    const float* d1_b2  = (const float*)d_in[map[9]];
    const float* d2_W1  = (const float*)d_in[map[10]];
    const float* d2_b1  = (const float*)d_in[map[11]];
    const float* d2_W2  = (const float*)d_in[map[12]];
    const float* d2_b2  = (const float*)d_in[map[13]];
    const float* s_W    = (const float*)d_in[map[14]];
    const float* s_b    = (const float*)d_in[map[15]];
    float* out = (float*)d_out;

    // outputs (tuple order, row-major each)
    float* o_zs   = out;                       // [N,32]
    float* o_zns  = out + (size_t)NN * 32;     // [N,32]
    float* o_xs   = out + (size_t)NN * 64;     // [N,256]
    float* o_xns  = o_xs + (size_t)NN * 256;   // [N,256]
    float* o_xscf = o_xns + (size_t)NN * 256;  // [N,256]
    float* o_s    = o_xscf + (size_t)NN * 256; // [N,N]  (written LAST)

    // large scratch carved out of the s_ region (SYRK overwrites it at the end)
    const size_t CH = (size_t)NN * 64;
    float* sc_y1   = o_s + 0 * CH;
    float* sc_A1   = o_s + 1 * CH;
    float* sc_h1   = o_s + 2 * CH;
    float* sc_h1cf = o_s + 3 * CH;
    float* sc_B    = o_s + 4 * CH;
    float* sc_Bcf  = o_s + 5 * CH;
    float* sc_z    = o_s + 6 * CH;
    float* sc_zcf  = o_s + 7 * CH;
    float* sc_t1   = o_s + 8 * CH;
    float* sc_t2   = o_s + 9 * CH;
    float* sc_t3   = o_s + 10 * CH;
    float* sc_at1  = o_s + 11 * CH;
    float* sc_at2  = o_s + 12 * CH;
    float* sc_at3  = o_s + 13 * CH;
    float* sc_az   = o_s + 14 * CH;
    float* sc_az2  = o_s + 14 * CH + (size_t)NN * 32;
    float* sc_azcf = o_s + 14 * CH + (size_t)NN * 64;

    const int TB = 256;
    const int gN    = (NN + TB - 1) / TB;
    const int gE    = (EE + TB - 1) / TB;
    const int gN32  = (NN * 32 + TB - 1) / TB;   // 1 warp/node kernels + split
    const int gN64  = (NN * 64 + TB - 1) / TB;

    // CSR build (by dst) with precomputed norms
    k_zero_deg<<<gN, TB>>>();
    k_count<<<gE, TB>>>(ei);
    k_dinv<<<gN, TB>>>();
    k_scan<<<1, 1024>>>();
    k_scatter<<<gE, TB>>>(ei);

    // encoder conv1: y1 = x@W1 ; A1 = agg(y1) ; rank-1 counterfactual path
    k_gemm4<INDIM, 64, false><<<(NN * 16 + TB - 1) / TB, TB>>>(x, enc_W1, nullptr, sc_y1);
    k_cvec<<<gN, TB>>>(x);
    k_agg64<<<gN32, TB>>>(sc_y1, sc_A1);
    k_aggscalar<<<gN32, TB>>>();
    k_h1<<<gN64, TB>>>(sc_A1, enc_W1, enc_b1, sc_h1, sc_h1cf);

    // encoder conv2: fused dual aggregation, then matmuls
    k_agg64x2<<<gN32, TB>>>(sc_h1, sc_h1cf, sc_B, sc_Bcf);
    k_gemm4<64, 64, false><<<(NN * 16 + TB - 1) / TB, TB>>>(sc_B, enc_W2, enc_b2, sc_z);
    k_gemm4<64, 64, false><<<(NN * 16 + TB - 1) / TB, TB>>>(sc_Bcf, enc_W2, enc_b2, sc_zcf);
    k_split<<<gN32, TB>>>(sc_z, o_zs, o_zns);

    // fused 96-dim aggregation of z_s / z_ns / z_s_cf
    k_agg96<<<gN32, TB>>>(sc_z, sc_zcf, sc_az, sc_az2, sc_azcf);

    // decoder first layers + hs
    k_gemm4<32, 64, true><<<(NN * 16 + TB - 1) / TB, TB>>>(sc_az, d1_W1, d1_b1, sc_t1);
    k_gemm4<32, 64, true><<<(NN * 16 + TB - 1) / TB, TB>>>(sc_az2, d2_W1, d2_b1, sc_t2);
    k_gemm4<32, 64, true><<<(NN * 16 + TB - 1) / TB, TB>>>(sc_azcf, d1_W1, d1_b1, sc_t3);
    k_gemm4<32, 64, false><<<(NN * 16 + TB - 1) / TB, TB>>>(sc_az2, s_W, s_b, g_hs);

    // fused triple aggregation of decoder hidden states
    k_agg64x3<<<gN32, TB>>>(sc_t1, sc_t2, sc_t3, sc_at1, sc_at2, sc_at3);

    // decoder output layers
    k_gemm4<64, 256, false><<<(NN * 64 + TB - 1) / TB, TB>>>(sc_at1, d1_W2, d1_b2, o_xs);
    k_gemm4<64, 256, false><<<(NN * 64 + TB - 1) / TB, TB>>>(sc_at2, d2_W2, d2_b2, o_xns);
    k_gemm4<64, 256, false><<<(NN * 64 + TB - 1) / TB, TB>>>(sc_at3, d1_W2, d1_b2, o_xscf);

    // s_ = hs @ hs^T — overwrites the entire scratch region last
    dim3 syrk_grid(NN / 64, NN / 64);
    k_syrk<<<syrk_grid, TB>>>(g_hs, o_s);
}

// round 5
// speedup vs baseline: 2.0818x; 1.4978x over previous
#include <cuda_runtime.h>

#define NN 12288
#define EE 393216
#define INDIM 256
#define HID 64

// ---------------- small static scratch (CSR + tiny vectors + hs) -------------
__device__ int   g_deg[NN];
__device__ float g_dinv[NN];
__device__ int   g_rowptr[NN + 1];
__device__ int   g_cursor[NN];
__device__ int   g_col[EE];
__device__ float g_val[EE];
__device__ float g_c[NN];
__device__ float g_aggc[NN];
__device__ float g_hs[NN * HID];   // read by SYRK while s_ region is overwritten

// ---------------- CSR build ---------------------------------------------------
__global__ void k_zero_deg() {
    int i = blockIdx.x * blockDim.x + threadIdx.x;
    if (i < NN) g_deg[i] = 0;
}
__global__ void k_count(const int* __restrict__ ei) {
    int e = blockIdx.x * blockDim.x + threadIdx.x;
    if (e < EE) atomicAdd(&g_deg[ei[EE + e]], 1);
}
__global__ void k_dinv() {
    int i = blockIdx.x * blockDim.x + threadIdx.x;
    if (i < NN) g_dinv[i] = rsqrtf((float)g_deg[i] + 1.0f);   // +1 self-loop
}
// parallel exclusive scan over NN = 1024*12 degrees (warp shuffles)
__global__ void k_scan() {
    __shared__ int wsum[32];
    int t = threadIdx.x;                 // 1024 threads
    int base = t * 12;
    int loc[12];
    int s = 0;
#pragma unroll
    for (int i = 0; i < 12; i++) { loc[i] = s; s += g_deg[base + i]; }
    int lane = t & 31, wid = t >> 5;
    int v = s;
#pragma unroll
    for (int o = 1; o < 32; o <<= 1) {
        int u = __shfl_up_sync(0xffffffffu, v, o);
        if (lane >= o) v += u;
    }
    if (lane == 31) wsum[wid] = v;
    __syncthreads();
    if (wid == 0) {
        int w = wsum[lane];
#pragma unroll
        for (int o = 1; o < 32; o <<= 1) {
            int u = __shfl_up_sync(0xffffffffu, w, o);
            if (lane >= o) w += u;
        }
        wsum[lane] = w;
    }
    __syncthreads();
    int excl = v - s + (wid > 0 ? wsum[wid - 1] : 0);
#pragma unroll
    for (int i = 0; i < 12; i++) {
        g_rowptr[base + i] = excl + loc[i];
        g_cursor[base + i] = excl + loc[i];
    }
    if (t == 1023) g_rowptr[NN] = excl + s;
}
__global__ void k_scatter(const int* __restrict__ ei) {
    int e = blockIdx.x * blockDim.x + threadIdx.x;
    if (e >= EE) return;
    int s = ei[e], d = ei[EE + e];
    int p = atomicAdd(&g_cursor[d], 1);
    g_col[p] = s;
    g_val[p] = g_dinv[s] * g_dinv[d];
}

// ---------------- deterministic CSR gather aggregations -----------------------
__global__ void k_agg64(const float* __restrict__ in, float* __restrict__ out) {
    int w = (blockIdx.x * 256 + threadIdx.x) >> 5;
    int lane = threadIdx.x & 31;
    if (w >= NN) return;
    int s0 = g_rowptr[w], s1 = g_rowptr[w + 1];
    float a0 = 0.f, a1 = 0.f;
    for (int j = s0; j < s1; j++) {
        int s = g_col[j];
        float wt = g_val[j];
        const float* p = in + s * 64;
        a0 += wt * p[lane];
        a1 += wt * p[32 + lane];
    }
    float ws = g_dinv[w] * g_dinv[w];
    const float* p = in + w * 64;
    a0 += ws * p[lane];
    a1 += ws * p[32 + lane];
    out[w * 64 + lane] = a0;
    out[w * 64 + 32 + lane] = a1;
}
__global__ void k_agg64x2(const float* __restrict__ in1, const float* __restrict__ in2,
                          float* __restrict__ out1, float* __restrict__ out2) {
    int w = (blockIdx.x * 256 + threadIdx.x) >> 5;
    int lane = threadIdx.x & 31;
    if (w >= NN) return;
    int s0 = g_rowptr[w], s1 = g_rowptr[w + 1];
    float a0 = 0.f, a1 = 0.f, b0 = 0.f, b1 = 0.f;
    for (int j = s0; j < s1; j++) {
        int s = g_col[j];
        float wt = g_val[j];
        const float* p1 = in1 + s * 64;
        const float* p2 = in2 + s * 64;
        a0 += wt * p1[lane];  a1 += wt * p1[32 + lane];
        b0 += wt * p2[lane];  b1 += wt * p2[32 + lane];
    }
    float ws = g_dinv[w] * g_dinv[w];
    const float* p1 = in1 + w * 64;
    const float* p2 = in2 + w * 64;
    a0 += ws * p1[lane];  a1 += ws * p1[32 + lane];
    b0 += ws * p2[lane];  b1 += ws * p2[32 + lane];
    out1[w * 64 + lane] = a0;  out1[w * 64 + 32 + lane] = a1;
    out2[w * 64 + lane] = b0;  out2[w * 64 + 32 + lane] = b1;
}
__global__ void k_agg64x3(const float* __restrict__ in1, const float* __restrict__ in2,
                          const float* __restrict__ in3, float* __restrict__ out1,
                          float* __restrict__ out2, float* __restrict__ out3) {
    int w = (blockIdx.x * 256 + threadIdx.x) >> 5;
    int lane = threadIdx.x & 31;
    if (w >= NN) return;
    int s0 = g_rowptr[w], s1 = g_rowptr[w + 1];
    float a0 = 0.f, a1 = 0.f, b0 = 0.f, b1 = 0.f, c0 = 0.f, c1 = 0.f;
    for (int j = s0; j < s1; j++) {
        int s = g_col[j];
        float wt = g_val[j];
        const float* p1 = in1 + s * 64;
        const float* p2 = in2 + s * 64;
        const float* p3 = in3 + s * 64;
        a0 += wt * p1[lane];  a1 += wt * p1[32 + lane];
        b0 += wt * p2[lane];  b1 += wt * p2[32 + lane];
        c0 += wt * p3[lane];  c1 += wt * p3[32 + lane];
    }
    float ws = g_dinv[w] * g_dinv[w];
    const float* p1 = in1 + w * 64;
    const float* p2 = in2 + w * 64;
    const float* p3 = in3 + w * 64;
    a0 += ws * p1[lane];  a1 += ws * p1[32 + lane];
    b0 += ws * p2[lane];  b1 += ws * p2[32 + lane];
    c0 += ws * p3[lane];  c1 += ws * p3[32 + lane];
    out1[w * 64 + lane] = a0;  out1[w * 64 + 32 + lane] = a1;
    out2[w * 64 + lane] = b0;  out2[w * 64 + 32 + lane] = b1;
    out3[w * 64 + lane] = c0;  out3[w * 64 + 32 + lane] = c1;
}
__global__ void k_agg96(const float* __restrict__ z, const float* __restrict__ zcf,
                        float* __restrict__ az, float* __restrict__ az2,
                        float* __restrict__ azcf) {
    int w = (blockIdx.x * 256 + threadIdx.x) >> 5;
    int lane = threadIdx.x & 31;
    if (w >= NN) return;
    int s0 = g_rowptr[w], s1 = g_rowptr[w + 1];
    float a0 = 0.f, a1 = 0.f, c0 = 0.f;
    for (int j = s0; j < s1; j++) {
        int s = g_col[j];
        float wt = g_val[j];
        const float* pz = z + s * 64;
        a0 += wt * pz[lane];
        a1 += wt * pz[32 + lane];
        c0 += wt * zcf[s * 64 + lane];
    }
    float ws = g_dinv[w] * g_dinv[w];
    const float* pz = z + w * 64;
    a0 += ws * pz[lane];
    a1 += ws * pz[32 + lane];
    c0 += ws * zcf[w * 64 + lane];
    az[w * 32 + lane] = a0;
    az2[w * 32 + lane] = a1;
    azcf[w * 32 + lane] = c0;
}
__global__ void k_aggscalar() {
    int w = (blockIdx.x * 256 + threadIdx.x) >> 5;
    int lane = threadIdx.x & 31;
    if (w >= NN) return;
    int s0 = g_rowptr[w], s1 = g_rowptr[w + 1];
    float a = 0.f;
    for (int j = s0 + lane; j < s1; j += 32)
        a += g_val[j] * g_c[g_col[j]];
#pragma unroll
    for (int o = 16; o; o >>= 1) a += __shfl_xor_sync(0xffffffffu, a, o);
    if (lane == 0) {
        float ws = g_dinv[w] * g_dinv[w];
        g_aggc[w] = a + ws * g_c[w];
    }
}

// ---------------- GEMM: out[N,KOUT] = A[N,KIN]@W[KIN,KOUT] (+b)(+relu) -------
// 4 outputs/thread; float4 loads on both A and W
template <int KIN, int KOUT, bool RELU>
__device__ __forceinline__ void gemm4_body(const float* __restrict__ A,
                                           const float* __restrict__ W,
                                           const float* __restrict__ b,
                                           float* __restrict__ out, int idx) {
    constexpr int C4 = KOUT / 4;
    if (idx >= NN * C4) return;
    int row = idx / C4, c4 = (idx % C4) * 4;
    float4 acc;
    if (b) { acc.x = b[c4]; acc.y = b[c4 + 1]; acc.z = b[c4 + 2]; acc.w = b[c4 + 3]; }
    else   { acc.x = acc.y = acc.z = acc.w = 0.f; }
    const float4* a4 = reinterpret_cast<const float4*>(A + row * KIN);
#pragma unroll 4
    for (int k4 = 0; k4 < KIN / 4; k4++) {
        float4 av = a4[k4];
        float4 w0 = *reinterpret_cast<const float4*>(&W[(k4 * 4 + 0) * KOUT + c4]);
        float4 w1 = *reinterpret_cast<const float4*>(&W[(k4 * 4 + 1) * KOUT + c4]);
        float4 w2 = *reinterpret_cast<const float4*>(&W[(k4 * 4 + 2) * KOUT + c4]);
        float4 w3 = *reinterpret_cast<const float4*>(&W[(k4 * 4 + 3) * KOUT + c4]);
        acc.x += av.x * w0.x + av.y * w1.x + av.z * w2.x + av.w * w3.x;
        acc.y += av.x * w0.y + av.y * w1.y + av.z * w2.y + av.w * w3.y;
        acc.z += av.x * w0.z + av.y * w1.z + av.z * w2.z + av.w * w3.z;
        acc.w += av.x * w0.w + av.y * w1.w + av.z * w2.w + av.w * w3.w;
    }
    if (RELU) {
        acc.x = fmaxf(acc.x, 0.f); acc.y = fmaxf(acc.y, 0.f);
        acc.z = fmaxf(acc.z, 0.f); acc.w = fmaxf(acc.w, 0.f);
    }
    *reinterpret_cast<float4*>(&out[row * KOUT + c4]) = acc;
}
template <int KIN, int KOUT, bool RELU>
__global__ void k_gemm4(const float* __restrict__ A, const float* __restrict__ W,
                        const float* __restrict__ b, float* __restrict__ out) {
    gemm4_body<KIN, KOUT, RELU>(A, W, b, out, blockIdx.x * 256 + threadIdx.x);
}
// three decoder output GEMMs (64 -> 256) in one launch; y picks the variant
__global__ void k_decout(const float* __restrict__ at1, const float* __restrict__ at2,
                         const float* __restrict__ at3,
                         const float* __restrict__ W1, const float* __restrict__ W2,
                         const float* __restrict__ b1, const float* __restrict__ b2,
                         float* __restrict__ o1, float* __restrict__ o2,
                         float* __restrict__ o3) {
    int v = blockIdx.y;
    const float* A = (v == 0) ? at1 : (v == 1) ? at2 : at3;
    const float* W = (v == 1) ? W2 : W1;
    const float* b = (v == 1) ? b2 : b1;
    float* out = (v == 0) ? o1 : (v == 1) ? o2 : o3;
    gemm4_body<64, 256, false>(A, W, b, out, blockIdx.x * 256 + threadIdx.x);
}

// ---------------- misc elementwise -------------------------------------------
__global__ void k_cvec(const float* __restrict__ x) {
    int i = blockIdx.x * blockDim.x + threadIdx.x;
    if (i < NN) g_c[i] = 1.0f - 2.0f * x[i * INDIM];
}
__global__ void k_h1(const float* __restrict__ A1, const float* __restrict__ W1,
                     const float* __restrict__ b1, float* __restrict__ h1,
                     float* __restrict__ h1cf) {
    int idx = blockIdx.x * blockDim.x + threadIdx.x;
    if (idx >= NN * HID) return;
    int i = idx >> 6, l = idx & 63;
    float base = A1[idx] + b1[l];
    h1[idx] = fmaxf(base, 0.f);
    h1cf[idx] = fmaxf(base + g_aggc[i] * W1[l], 0.f);
}
__global__ void k_split(const float* __restrict__ z, float* __restrict__ ozs,
                        float* __restrict__ ozns) {
    int idx = blockIdx.x * blockDim.x + threadIdx.x;
    if (idx >= NN * 32) return;
    int i = idx >> 5, l = idx & 31;
    ozs[idx] = z[i * 64 + l];
    ozns[idx] = z[i * 64 + 32 + l];
}

// ---------------- SYRK: 128x128 tiles, 8x8 micro-tile, FFMA-bound ------------
// dynamic smem pool (66048 B): compute phase = sA[64][129] + sB[64][129];
// mirror phase reuses the whole pool as stage[128][129].
__global__ void __launch_bounds__(256) k_syrk128(const float* __restrict__ hs,
                                                 float* __restrict__ C) {
    int bi = blockIdx.y, bj = blockIdx.x;
    if (bj < bi) return;
    extern __shared__ float pool[];
    float* sA = pool;          // [64 k][129]
    float* sB = pool + 8256;   // [64 k][129]
    int tid = threadIdx.x;
    int r0 = tid >> 4;          // 0..15
    int k4 = (tid & 15) * 4;    // 0..60 step 4

    // load + transpose both tiles: 8 passes of 16 rows each
#pragma unroll
    for (int pass = 0; pass < 8; pass++) {
        int r = pass * 16 + r0;
        float4 va = *reinterpret_cast<const float4*>(&hs[(size_t)(bi * 128 + r) * 64 + k4]);
        sA[(k4 + 0) * 129 + r] = va.x;
        sA[(k4 + 1) * 129 + r] = va.y;
        sA[(k4 + 2) * 129 + r] = va.z;
        sA[(k4 + 3) * 129 + r] = va.w;
        float4 vb = *reinterpret_cast<const float4*>(&hs[(size_t)(bj * 128 + r) * 64 + k4]);
        sB[(k4 + 0) * 129 + r] = vb.x;
        sB[(k4 + 1) * 129 + r] = vb.y;
        sB[(k4 + 2) * 129 + r] = vb.z;
        sB[(k4 + 3) * 129 + r] = vb.w;
    }
    __syncthreads();

    int tx = tid & 15, ty = tid >> 4;
    int ry = ty * 4, rx = tx * 4;     // rows {ry..ry+3, 64+ry..}, cols likewise
    float acc[8][8];
#pragma unroll
    for (int i = 0; i < 8; i++)
#pragma unroll
        for (int j = 0; j < 8; j++) acc[i][j] = 0.f;

#pragma unroll 2
    for (int k = 0; k < 64; k++) {
        float a[8], b[8];
#pragma unroll
        for (int i = 0; i < 4; i++) {
            a[i]     = sA[k * 129 + ry + i];
            a[i + 4] = sA[k * 129 + 64 + ry + i];
            b[i]     = sB[k * 129 + rx + i];
            b[i + 4] = sB[k * 129 + 64 + rx + i];
        }
#pragma unroll
        for (int i = 0; i < 8; i++)
#pragma unroll
            for (int j = 0; j < 8; j++) acc[i][j] += a[i] * b[j];
    }

    // direct stores (upper tile), float4 per 4 cols
#pragma unroll
    for (int i = 0; i < 8; i++) {
        int row = bi * 128 + (i < 4 ? ry + i : 64 + ry + i - 4);
        float4 v0, v1;
        v0.x = acc[i][0]; v0.y = acc[i][1]; v0.z = acc[i][2]; v0.w = acc[i][3];
        v1.x = acc[i][4]; v1.y = acc[i][5]; v1.z = acc[i][6]; v1.w = acc[i][7];
        *reinterpret_cast<float4*>(&C[(size_t)row * NN + bj * 128 + rx]) = v0;
        *reinterpret_cast<float4*>(&C[(size_t)row * NN + bj * 128 + 64 + rx]) = v1;
    }

    if (bi != bj) {   // mirrored tile via smem staging (coalesced stores)
        __syncthreads();
        float* sT = pool;   // [128 c][129]
#pragma unroll
        for (int i = 0; i < 8; i++) {
            int r = (i < 4 ? ry + i : 64 + ry + i - 4);
#pragma unroll
            for (int j = 0; j < 8; j++) {
                int c = (j < 4 ? rx + j : 64 + rx + j - 4);
                sT[c * 129 + r] = acc[i][j];
            }
        }
        __syncthreads();
        for (int idx = tid; idx < 128 * 128; idx += 256) {
            int r2 = idx >> 7, c2 = idx & 127;
            C[(size_t)(bj * 128 + r2) * NN + bi * 128 + c2] = sT[r2 * 129 + c2];
        }
    }
}

// ---------------- input-order hypotheses (round-3 validated) ------------------
static const int SIGS[6][16] = {
  {3145728,786432,16384,64,4096,64,2048,64,16384,256,2048,64,16384,256,2048,64},
  {2048,16384,64,256,2048,16384,64,256,786432,16384,4096,64,64,2048,64,3145728},
  {64,256,2048,16384,64,256,2048,16384,786432,64,64,16384,4096,64,2048,3145728},
  {64,2048,256,16384,64,2048,256,16384,64,2048,64,4096,64,16384,786432,3145728},
  {3145728,786432,16384,16384,16384,4096,2048,2048,2048,256,256,64,64,64,64,64},
  {64,64,64,64,64,256,256,2048,2048,2048,4096,16384,16384,16384,786432,3145728},
};
static const int MAPS[6][16] = {
  {0,1,2,3,4,5,6,7,8,9,10,11,12,13,14,15},
  {15,8,9,11,10,12,0,2,1,3,4,6,5,7,13,14},
  {15,8,11,9,12,10,2,0,3,1,6,4,7,5,14,13},
  {15,14,13,12,11,10,9,8,7,6,5,4,3,2,1,0},
  {0,1,2,11,5,12,6,13,3,9,7,14,4,10,8,15},
  {15,14,11,0,10,1,7,2,12,5,8,3,13,6,9,4},
};

// ---------------- launch ------------------------------------------------------
extern "C" void kernel_launch(void* const* d_in, const int* in_sizes, int n_in,
                              void* d_out, int out_size) {
    const int* map = MAPS[0];
    for (int h = 0; h < 6; h++) {
        bool ok = (n_in >= 16);
        for (int i = 0; ok && i < 16; i++) ok = (in_sizes[i] == SIGS[h][i]);
        if (ok) { map = MAPS[h]; break; }
    }
    const float* x      = (const float*)d_in[map[0]];
    const int*   ei     = (const int*)  d_in[map[1]];
    const float* enc_W1 = (const float*)d_in[map[2]];
    const float* enc_b1 = (const float*)d_in[map[3]];
    const float* enc_W2 = (const float*)d_in[map[4]];
    const float* enc_b2 = (const float*)d_in[map[5]];
    const float* d1_W1  = (const float*)d_in[map[6]];
    const float* d1_b1  = (const float*)d_in[map[7]];
    const float* d1_W2  = (const float*)d_in[map[8]];
    const float* d1_b2  = (const float*)d_in[map[9]];
    const float* d2_W1  = (const float*)d_in[map[10]];
    const float* d2_b1  = (const float*)d_in[map[11]];
    const float* d2_W2  = (const float*)d_in[map[12]];
    const float* d2_b2  = (const float*)d_in[map[13]];
    const float* s_W    = (const float*)d_in[map[14]];
    const float* s_b    = (const float*)d_in[map[15]];
    float* out = (float*)d_out;

    float* o_zs   = out;
    float* o_zns  = out + (size_t)NN * 32;
    float* o_xs   = out + (size_t)NN * 64;
    float* o_xns  = o_xs + (size_t)NN * 256;
    float* o_xscf = o_xns + (size_t)NN * 256;
    float* o_s    = o_xscf + (size_t)NN * 256;   // [N,N] written LAST

    const size_t CH = (size_t)NN * 64;
    float* sc_y1   = o_s + 0 * CH;
    float* sc_A1   = o_s + 1 * CH;
    float* sc_h1   = o_s + 2 * CH;
    float* sc_h1cf = o_s + 3 * CH;
    float* sc_B    = o_s + 4 * CH;
    float* sc_Bcf  = o_s + 5 * CH;
    float* sc_z    = o_s + 6 * CH;
    float* sc_zcf  = o_s + 7 * CH;
    float* sc_t1   = o_s + 8 * CH;
    float* sc_t2   = o_s + 9 * CH;
    float* sc_t3   = o_s + 10 * CH;
    float* sc_at1  = o_s + 11 * CH;
    float* sc_at2  = o_s + 12 * CH;
    float* sc_at3  = o_s + 13 * CH;
    float* sc_az   = o_s + 14 * CH;
    float* sc_az2  = o_s + 14 * CH + (size_t)NN * 32;
    float* sc_azcf = o_s + 14 * CH + (size_t)NN * 64;

    const int TB = 256;
    const int gN   = (NN + TB - 1) / TB;
    const int gE   = (EE + TB - 1) / TB;
    const int gN32 = (NN * 32 + TB - 1) / TB;
    const int gN64 = (NN * 64 + TB - 1) / TB;
    const int gN16 = (NN * 16 + TB - 1) / TB;

    static bool attr_done = false;
    if (!attr_done) {
        cudaFuncSetAttribute(k_syrk128, cudaFuncAttributeMaxDynamicSharedMemorySize,
                             66048);
        attr_done = true;
    }

    // CSR build (by dst) with precomputed norms
    k_zero_deg<<<gN, TB>>>();
    k_count<<<gE, TB>>>(ei);
    k_dinv<<<gN, TB>>>();
    k_scan<<<1, 1024>>>();
    k_scatter<<<gE, TB>>>(ei);

    // encoder conv1
    k_gemm4<INDIM, 64, false><<<gN16, TB>>>(x, enc_W1, nullptr, sc_y1);
    k_cvec<<<gN, TB>>>(x);
    k_agg64<<<gN32, TB>>>(sc_y1, sc_A1);
    k_aggscalar<<<gN32, TB>>>();
    k_h1<<<gN64, TB>>>(sc_A1, enc_W1, enc_b1, sc_h1, sc_h1cf);

    // encoder conv2
    k_agg64x2<<<gN32, TB>>>(sc_h1, sc_h1cf, sc_B, sc_Bcf);
    k_gemm4<64, 64, false><<<gN16, TB>>>(sc_B, enc_W2, enc_b2, sc_z);
    k_gemm4<64, 64, false><<<gN16, TB>>>(sc_Bcf, enc_W2, enc_b2, sc_zcf);
    k_split<<<gN32, TB>>>(sc_z, o_zs, o_zns);

    // fused aggregation of z_s / z_ns / z_s_cf
    k_agg96<<<gN32, TB>>>(sc_z, sc_zcf, sc_az, sc_az2, sc_azcf);

    // decoder first layers + hs
    k_gemm4<32, 64, true><<<gN16, TB>>>(sc_az, d1_W1, d1_b1, sc_t1);
    k_gemm4<32, 64, true><<<gN16, TB>>>(sc_az2, d2_W1, d2_b1, sc_t2);
    k_gemm4<32, 64, true><<<gN16, TB>>>(sc_azcf, d1_W1, d1_b1, sc_t3);
    k_gemm4<32, 64, false><<<gN16, TB>>>(sc_az2, s_W, s_b, g_hs);

    // fused triple aggregation of decoder hidden states
    k_agg64x3<<<gN32, TB>>>(sc_t1, sc_t2, sc_t3, sc_at1, sc_at2, sc_at3);

    // decoder output layers (one launch, 3 variants)
    dim3 dog(gN64, 3);
    k_decout<<<dog, TB>>>(sc_at1, sc_at2, sc_at3, d1_W2, d2_W2, d1_b2, d2_b2,
                          o_xs, o_xns, o_xscf);

    // s_ = hs @ hs^T (128x128 tiles, symmetric)
    dim3 syrk_grid(NN / 128, NN / 128);
    k_syrk128<<<syrk_grid, TB, 66048>>>(g_hs, o_s);
}

// round 9
// speedup vs baseline: 8.6403x; 4.1504x over previous
#include <cuda_runtime.h>
#include <cuda_bf16.h>
#include <cstdint>

#define NN 12288
#define EE 393216
#define INDIM 256
#define HID 64

// ---------------- static device scratch (device-code references ONLY) ---------
__device__ int   g_deg[NN];
__device__ float g_dinv[NN];
__device__ int   g_rowptr[NN + 1];
__device__ int   g_cursor[NN];
__device__ int   g_col[EE];
__device__ float g_val[EE];
__device__ float g_c[NN];
__device__ float g_aggc[NN];
__device__ __nv_bfloat16 g_hshi[NN * HID];
__device__ __nv_bfloat16 g_hslo[NN * HID];

// ---------------- CSR build ---------------------------------------------------
__global__ void k_zero_deg() {
    int i = blockIdx.x * blockDim.x + threadIdx.x;
    if (i < NN) g_deg[i] = 0;
}
__global__ void k_count(const int* __restrict__ ei) {
    int e = blockIdx.x * blockDim.x + threadIdx.x;
    if (e < EE) atomicAdd(&g_deg[ei[EE + e]], 1);
}
__global__ void k_dinv() {
    int i = blockIdx.x * blockDim.x + threadIdx.x;
    if (i < NN) g_dinv[i] = rsqrtf((float)g_deg[i] + 1.0f);
}
__global__ void k_scan() {
    __shared__ int wsum[32];
    int t = threadIdx.x;
    int base = t * 12;
    int loc[12];
    int s = 0;
#pragma unroll
    for (int i = 0; i < 12; i++) { loc[i] = s; s += g_deg[base + i]; }
    int lane = t & 31, wid = t >> 5;
    int v = s;
#pragma unroll
    for (int o = 1; o < 32; o <<= 1) {
        int u = __shfl_up_sync(0xffffffffu, v, o);
        if (lane >= o) v += u;
    }
    if (lane == 31) wsum[wid] = v;
    __syncthreads();
    if (wid == 0) {
        int w = wsum[lane];
#pragma unroll
        for (int o = 1; o < 32; o <<= 1) {
            int u = __shfl_up_sync(0xffffffffu, w, o);
            if (lane >= o) w += u;
        }
        wsum[lane] = w;
    }
    __syncthreads();
    int excl = v - s + (wid > 0 ? wsum[wid - 1] : 0);
#pragma unroll
    for (int i = 0; i < 12; i++) {
        g_rowptr[base + i] = excl + loc[i];
        g_cursor[base + i] = excl + loc[i];
    }
    if (t == 1023) g_rowptr[NN] = excl + s;
}
__global__ void k_scatter(const int* __restrict__ ei) {
    int e = blockIdx.x * blockDim.x + threadIdx.x;
    if (e >= EE) return;
    int s = ei[e], d = ei[EE + e];
    int p = atomicAdd(&g_cursor[d], 1);
    g_col[p] = s;
    g_val[p] = g_dinv[s] * g_dinv[d];
}

// ---------------- CSR gather aggregations (float2 lanes) ----------------------
__global__ void k_agg64c(const float* __restrict__ in, float* __restrict__ out) {
    int w = (blockIdx.x * 256 + threadIdx.x) >> 5;
    int lane = threadIdx.x & 31;
    if (w >= NN) return;
    int s0 = g_rowptr[w], s1 = g_rowptr[w + 1];
    float2 a = make_float2(0.f, 0.f);
    float cacc = 0.f;
    for (int j = s0; j < s1; j++) {
        int s = g_col[j];
        float wt = g_val[j];
        float2 v = reinterpret_cast<const float2*>(in + s * 64)[lane];
        a.x += wt * v.x;  a.y += wt * v.y;
        cacc += wt * g_c[s];
    }
    float ws = g_dinv[w] * g_dinv[w];
    float2 v = reinterpret_cast<const float2*>(in + w * 64)[lane];
    a.x += ws * v.x;  a.y += ws * v.y;
    reinterpret_cast<float2*>(out + w * 64)[lane] = a;
    if (lane == 0) g_aggc[w] = cacc + ws * g_c[w];
}
__global__ void k_agg64x2(const float* __restrict__ in1, const float* __restrict__ in2,
                          float* __restrict__ out1, float* __restrict__ out2) {
    int w = (blockIdx.x * 256 + threadIdx.x) >> 5;
    int lane = threadIdx.x & 31;
    if (w >= NN) return;
    int s0 = g_rowptr[w], s1 = g_rowptr[w + 1];
    float2 a = make_float2(0.f, 0.f), b = make_float2(0.f, 0.f);
    for (int j = s0; j < s1; j++) {
        int s = g_col[j];
        float wt = g_val[j];
        float2 v1 = reinterpret_cast<const float2*>(in1 + s * 64)[lane];
        float2 v2 = reinterpret_cast<const float2*>(in2 + s * 64)[lane];
        a.x += wt * v1.x;  a.y += wt * v1.y;
        b.x += wt * v2.x;  b.y += wt * v2.y;
    }
    float ws = g_dinv[w] * g_dinv[w];
    float2 v1 = reinterpret_cast<const float2*>(in1 + w * 64)[lane];
    float2 v2 = reinterpret_cast<const float2*>(in2 + w * 64)[lane];
    a.x += ws * v1.x;  a.y += ws * v1.y;
    b.x += ws * v2.x;  b.y += ws * v2.y;
    reinterpret_cast<float2*>(out1 + w * 64)[lane] = a;
    reinterpret_cast<float2*>(out2 + w * 64)[lane] = b;
}
__global__ void k_agg64x3(const float* __restrict__ in1, const float* __restrict__ in2,
                          const float* __restrict__ in3, float* __restrict__ out1,
                          float* __restrict__ out2, float* __restrict__ out3) {
    int w = (blockIdx.x * 256 + threadIdx.x) >> 5;
    int lane = threadIdx.x & 31;
    if (w >= NN) return;
    int s0 = g_rowptr[w], s1 = g_rowptr[w + 1];
    float2 a = make_float2(0.f, 0.f), b = make_float2(0.f, 0.f), c = make_float2(0.f, 0.f);
    for (int j = s0; j < s1; j++) {
        int s = g_col[j];
        float wt = g_val[j];
        float2 v1 = reinterpret_cast<const float2*>(in1 + s * 64)[lane];
        float2 v2 = reinterpret_cast<const float2*>(in2 + s * 64)[lane];
        float2 v3 = reinterpret_cast<const float2*>(in3 + s * 64)[lane];
        a.x += wt * v1.x;  a.y += wt * v1.y;
        b.x += wt * v2.x;  b.y += wt * v2.y;
        c.x += wt * v3.x;  c.y += wt * v3.y;
    }
    float ws = g_dinv[w] * g_dinv[w];
    float2 v1 = reinterpret_cast<const float2*>(in1 + w * 64)[lane];
    float2 v2 = reinterpret_cast<const float2*>(in2 + w * 64)[lane];
    float2 v3 = reinterpret_cast<const float2*>(in3 + w * 64)[lane];
    a.x += ws * v1.x;  a.y += ws * v1.y;
    b.x += ws * v2.x;  b.y += ws * v2.y;
    c.x += ws * v3.x;  c.y += ws * v3.y;
    reinterpret_cast<float2*>(out1 + w * 64)[lane] = a;
    reinterpret_cast<float2*>(out2 + w * 64)[lane] = b;
    reinterpret_cast<float2*>(out3 + w * 64)[lane] = c;
}
__global__ void k_agg96(const float* __restrict__ z, const float* __restrict__ zcf,
                        float* __restrict__ az, float* __restrict__ az2,
                        float* __restrict__ azcf) {
    int w = (blockIdx.x * 256 + threadIdx.x) >> 5;
    int lane = threadIdx.x & 31;
    if (w >= NN) return;
    int s0 = g_rowptr[w], s1 = g_rowptr[w + 1];
    float2 a = make_float2(0.f, 0.f);
    float c0 = 0.f;
    for (int j = s0; j < s1; j++) {
        int s = g_col[j];
        float wt = g_val[j];
        float2 v = reinterpret_cast<const float2*>(z + s * 64)[lane];
        a.x += wt * v.x;  a.y += wt * v.y;
        c0 += wt * zcf[s * 64 + lane];
    }
    float ws = g_dinv[w] * g_dinv[w];
    float2 v = reinterpret_cast<const float2*>(z + w * 64)[lane];
    a.x += ws * v.x;  a.y += ws * v.y;
    c0 += ws * zcf[w * 64 + lane];
    if (lane < 16) reinterpret_cast<float2*>(az + w * 32)[lane] = a;
    else           reinterpret_cast<float2*>(az2 + w * 32)[lane - 16] = a;
    azcf[w * 32 + lane] = c0;
}

// ---------------- GEMM bodies -------------------------------------------------
template <int KIN, int KOUT>
__device__ __forceinline__ float4 gemm4_compute(const float* __restrict__ A,
                                                const float* __restrict__ W,
                                                const float* __restrict__ b,
                                                int row, int c4) {
    float4 acc;
    if (b) { acc.x = b[c4]; acc.y = b[c4 + 1]; acc.z = b[c4 + 2]; acc.w = b[c4 + 3]; }
    else   { acc.x = acc.y = acc.z = acc.w = 0.f; }
    const float4* a4 = reinterpret_cast<const float4*>(A + row * KIN);
#pragma unroll 4
    for (int k4 = 0; k4 < KIN / 4; k4++) {
        float4 av = a4[k4];
        float4 w0 = *reinterpret_cast<const float4*>(&W[(k4 * 4 + 0) * KOUT + c4]);
        float4 w1 = *reinterpret_cast<const float4*>(&W[(k4 * 4 + 1) * KOUT + c4]);
        float4 w2 = *reinterpret_cast<const float4*>(&W[(k4 * 4 + 2) * KOUT + c4]);
        float4 w3 = *reinterpret_cast<const float4*>(&W[(k4 * 4 + 3) * KOUT + c4]);
        acc.x += av.x * w0.x + av.y * w1.x + av.z * w2.x + av.w * w3.x;
        acc.y += av.x * w0.y + av.y * w1.y + av.z * w2.y + av.w * w3.y;
        acc.z += av.x * w0.z + av.y * w1.z + av.z * w2.z + av.w * w3.z;
        acc.w += av.x * w0.w + av.y * w1.w + av.z * w2.w + av.w * w3.w;
    }
    return acc;
}
template <int KIN, int KOUT, bool RELU>
__global__ void k_gemm4(const float* __restrict__ A, const float* __restrict__ W,
                        const float* __restrict__ b, float* __restrict__ out) {
    constexpr int C4 = KOUT / 4;
    int idx = blockIdx.x * 256 + threadIdx.x;
    if (idx >= NN * C4) return;
    int row = idx / C4, c4 = (idx % C4) * 4;
    float4 acc = gemm4_compute<KIN, KOUT>(A, W, b, row, c4);
    if (RELU) {
        acc.x = fmaxf(acc.x, 0.f); acc.y = fmaxf(acc.y, 0.f);
        acc.z = fmaxf(acc.z, 0.f); acc.w = fmaxf(acc.w, 0.f);
    }
    *reinterpret_cast<float4*>(&out[row * KOUT + c4]) = acc;
}
// four 32->64 GEMMs in one launch; v==3 (hs) writes bf16 hi/lo DEVICE SYMBOLS
__global__ void k_dec1(const float* __restrict__ az, const float* __restrict__ az2,
                       const float* __restrict__ azcf,
                       const float* __restrict__ d1W1, const float* __restrict__ d1b1,
                       const float* __restrict__ d2W1, const float* __restrict__ d2b1,
                       const float* __restrict__ sW, const float* __restrict__ sb,
                       float* __restrict__ t1, float* __restrict__ t2,
                       float* __restrict__ t3) {
    int v = blockIdx.y;
    int idx = blockIdx.x * 256 + threadIdx.x;
    if (idx >= NN * 16) return;
    int row = idx / 16, c4 = (idx % 16) * 4;
    const float* A = (v == 0) ? az : (v == 2) ? azcf : az2;
    const float* W = (v == 1) ? d2W1 : (v == 3) ? sW : d1W1;
    const float* b = (v == 1) ? d2b1 : (v == 3) ? sb : d1b1;
    float4 acc = gemm4_compute<32, 64>(A, W, b, row, c4);
    if (v == 3) {
        // split into bf16 hi/lo for tensor-core SYRK (device-symbol writes)
        float vals[4] = {acc.x, acc.y, acc.z, acc.w};
#pragma unroll
        for (int q = 0; q < 4; q++) {
            __nv_bfloat16 hi = __float2bfloat16(vals[q]);
            g_hshi[row * 64 + c4 + q] = hi;
            g_hslo[row * 64 + c4 + q] = __float2bfloat16(vals[q] - __bfloat162float(hi));
        }
    } else {
        acc.x = fmaxf(acc.x, 0.f); acc.y = fmaxf(acc.y, 0.f);
        acc.z = fmaxf(acc.z, 0.f); acc.w = fmaxf(acc.w, 0.f);
        float* out = (v == 0) ? t1 : (v == 1) ? t2 : t3;
        *reinterpret_cast<float4*>(&out[row * 64 + c4]) = acc;
    }
}
// three 64->256 GEMMs in one launch
__global__ void k_decout(const float* __restrict__ at1, const float* __restrict__ at2,
                         const float* __restrict__ at3,
                         const float* __restrict__ W1, const float* __restrict__ W2,
                         const float* __restrict__ b1, const float* __restrict__ b2,
                         float* __restrict__ o1, float* __restrict__ o2,
                         float* __restrict__ o3) {
    int v = blockIdx.y;
    int idx = blockIdx.x * 256 + threadIdx.x;
    if (idx >= NN * 64) return;
    int row = idx / 64, c4 = (idx % 64) * 4;
    const float* A = (v == 0) ? at1 : (v == 1) ? at2 : at3;
    const float* W = (v == 1) ? W2 : W1;
    const float* b = (v == 1) ? b2 : b1;
    float* out = (v == 0) ? o1 : (v == 1) ? o2 : o3;
    float4 acc = gemm4_compute<64, 256>(A, W, b, row, c4);
    *reinterpret_cast<float4*>(&out[row * 256 + c4]) = acc;
}

// ---------------- misc elementwise -------------------------------------------
__global__ void k_cvec(const float* __restrict__ x) {
    int i = blockIdx.x * blockDim.x + threadIdx.x;
    if (i < NN) g_c[i] = 1.0f - 2.0f * x[i * INDIM];
}
__global__ void k_h1(const float* __restrict__ A1, const float* __restrict__ W1,
                     const float* __restrict__ b1, float* __restrict__ h1,
                     float* __restrict__ h1cf) {
    int idx = blockIdx.x * blockDim.x + threadIdx.x;
    if (idx >= NN * HID) return;
    int i = idx >> 6, l = idx & 63;
    float base = A1[idx] + b1[l];
    h1[idx] = fmaxf(base, 0.f);
    h1cf[idx] = fmaxf(base + g_aggc[i] * W1[l], 0.f);
}
__global__ void k_split(const float* __restrict__ z, float* __restrict__ ozs,
                        float* __restrict__ ozns) {
    int idx = blockIdx.x * blockDim.x + threadIdx.x;
    if (idx >= NN * 32) return;
    int i = idx >> 5, l = idx & 31;
    ozs[idx] = z[i * 64 + l];
    ozns[idx] = z[i * 64 + 32 + l];
}

// ---------------- SYRK via mma.sync bf16 (hi/lo 3-product compensation) -------
#define SPITCH 72
#define TBYTES (128 * SPITCH * 2)   // 18432
#define OPITCH 133                  // epilogue stage pitch (gcd(5,32)=1)

static __device__ __forceinline__ void mma_bf16(float* d, const uint32_t* a,
                                                uint32_t b0, uint32_t b1) {
    asm volatile(
        "mma.sync.aligned.m16n8k16.row.col.f32.bf16.bf16.f32 "
        "{%0,%1,%2,%3}, {%4,%5,%6,%7}, {%8,%9}, {%0,%1,%2,%3};"
        : "+f"(d[0]), "+f"(d[1]), "+f"(d[2]), "+f"(d[3])
        : "r"(a[0]), "r"(a[1]), "r"(a[2]), "r"(a[3]), "r"(b0), "r"(b1));
}

__global__ void __launch_bounds__(256) k_syrk_mma(float* __restrict__ C) {
    int bi = blockIdx.y, bj = blockIdx.x;
    if (bj < bi) return;
    extern __shared__ char smem[];
    __nv_bfloat16* sAhi = reinterpret_cast<__nv_bfloat16*>(smem);
    __nv_bfloat16* sAlo = reinterpret_cast<__nv_bfloat16*>(smem + TBYTES);
    __nv_bfloat16* sBhi = reinterpret_cast<__nv_bfloat16*>(smem + 2 * TBYTES);
    __nv_bfloat16* sBlo = reinterpret_cast<__nv_bfloat16*>(smem + 3 * TBYTES);
    int tid = threadIdx.x;

    {
        const uint4* ga_hi = reinterpret_cast<const uint4*>(g_hshi + (size_t)bi * 128 * 64);
        const uint4* ga_lo = reinterpret_cast<const uint4*>(g_hslo + (size_t)bi * 128 * 64);
        const uint4* gb_hi = reinterpret_cast<const uint4*>(g_hshi + (size_t)bj * 128 * 64);
        const uint4* gb_lo = reinterpret_cast<const uint4*>(g_hslo + (size_t)bj * 128 * 64);
        for (int idx = tid; idx < 1024; idx += 256) {
            int row = idx >> 3, ch = idx & 7;
            int so = row * SPITCH + ch * 8;
            *reinterpret_cast<uint4*>(sAhi + so) = ga_hi[idx];
            *reinterpret_cast<uint4*>(sAlo + so) = ga_lo[idx];
            *reinterpret_cast<uint4*>(sBhi + so) = gb_hi[idx];
            *reinterpret_cast<uint4*>(sBlo + so) = gb_lo[idx];
        }
    }
    __syncthreads();

    int wid = tid >> 5, lane = tid & 31;
    int wr = wid >> 1, wc = wid & 1;
    int g = lane >> 2, tg = lane & 3;

    float acc[2][8][4];
#pragma unroll
    for (int mt = 0; mt < 2; mt++)
#pragma unroll
        for (int nt = 0; nt < 8; nt++)
#pragma unroll
            for (int q = 0; q < 4; q++) acc[mt][nt][q] = 0.f;

#pragma unroll
    for (int ks = 0; ks < 4; ks++) {
        int k0 = ks * 16;
        uint32_t aHi[2][4], aLo[2][4];
#pragma unroll
        for (int mt = 0; mt < 2; mt++) {
            int r = wr * 32 + mt * 16;
            aHi[mt][0] = *reinterpret_cast<const uint32_t*>(&sAhi[(r + g) * SPITCH + k0 + tg * 2]);
            aHi[mt][1] = *reinterpret_cast<const uint32_t*>(&sAhi[(r + g + 8) * SPITCH + k0 + tg * 2]);
            aHi[mt][2] = *reinterpret_cast<const uint32_t*>(&sAhi[(r + g) * SPITCH + k0 + tg * 2 + 8]);
            aHi[mt][3] = *reinterpret_cast<const uint32_t*>(&sAhi[(r + g + 8) * SPITCH + k0 + tg * 2 + 8]);
            aLo[mt][0] = *reinterpret_cast<const uint32_t*>(&sAlo[(r + g) * SPITCH + k0 + tg * 2]);
            aLo[mt][1] = *reinterpret_cast<const uint32_t*>(&sAlo[(r + g + 8) * SPITCH + k0 + tg * 2]);
            aLo[mt][2] = *reinterpret_cast<const uint32_t*>(&sAlo[(r + g) * SPITCH + k0 + tg * 2 + 8]);
            aLo[mt][3] = *reinterpret_cast<const uint32_t*>(&sAlo[(r + g + 8) * SPITCH + k0 + tg * 2 + 8]);
        }
#pragma unroll
        for (int nt = 0; nt < 8; nt++) {
            int n = wc * 64 + nt * 8 + g;
            uint32_t bh0 = *reinterpret_cast<const uint32_t*>(&sBhi[n * SPITCH + k0 + tg * 2]);
            uint32_t bh1 = *reinterpret_cast<const uint32_t*>(&sBhi[n * SPITCH + k0 + tg * 2 + 8]);
            uint32_t bl0 = *reinterpret_cast<const uint32_t*>(&sBlo[n * SPITCH + k0 + tg * 2]);
            uint32_t bl1 = *reinterpret_cast<const uint32_t*>(&sBlo[n * SPITCH + k0 + tg * 2 + 8]);
#pragma unroll
            for (int mt = 0; mt < 2; mt++) {
                mma_bf16(acc[mt][nt], aHi[mt], bh0, bh1);
                mma_bf16(acc[mt][nt], aHi[mt], bl0, bl1);
                mma_bf16(acc[mt][nt], aLo[mt], bh0, bh1);
            }
        }
    }
    __syncthreads();   // tiles no longer needed; pool becomes the stage buffer

    float* stage = reinterpret_cast<float*>(smem);   // [128][OPITCH]
#pragma unroll
    for (int mt = 0; mt < 2; mt++) {
        int r = wr * 32 + mt * 16 + g;
#pragma unroll
        for (int nt = 0; nt < 8; nt++) {
            int cc = wc * 64 + nt * 8 + tg * 2;
            stage[r * OPITCH + cc]           = acc[mt][nt][0];
            stage[r * OPITCH + cc + 1]       = acc[mt][nt][1];
            stage[(r + 8) * OPITCH + cc]     = acc[mt][nt][2];
            stage[(r + 8) * OPITCH + cc + 1] = acc[mt][nt][3];
        }
    }
    __syncthreads();

    for (int idx = tid; idx < 128 * 128; idx += 256) {
        int r2 = idx >> 7, c2 = idx & 127;
        C[(size_t)(bi * 128 + r2) * NN + bj * 128 + c2] = stage[r2 * OPITCH + c2];
    }
    if (bi != bj) {
        for (int idx = tid; idx < 128 * 128; idx += 256) {
            int r2 = idx >> 7, c2 = idx & 127;
            C[(size_t)(bj * 128 + r2) * NN + bi * 128 + c2] = stage[c2 * OPITCH + r2];
        }
    }
}

// ---------------- input-order hypotheses (round-3 validated) ------------------
static const int SIGS[6][16] = {
  {3145728,786432,16384,64,4096,64,2048,64,16384,256,2048,64,16384,256,2048,64},
  {2048,16384,64,256,2048,16384,64,256,786432,16384,4096,64,64,2048,64,3145728},
  {64,256,2048,16384,64,256,2048,16384,786432,64,64,16384,4096,64,2048,3145728},
  {64,2048,256,16384,64,2048,256,16384,64,2048,64,4096,64,16384,786432,3145728},
  {3145728,786432,16384,16384,16384,4096,2048,2048,2048,256,256,64,64,64,64,64},
  {64,64,64,64,64,256,256,2048,2048,2048,4096,16384,16384,16384,786432,3145728},
};
static const int MAPS[6][16] = {
  {0,1,2,3,4,5,6,7,8,9,10,11,12,13,14,15},
  {15,8,9,11,10,12,0,2,1,3,4,6,5,7,13,14},
  {15,8,11,9,12,10,2,0,3,1,6,4,7,5,14,13},
  {15,14,13,12,11,10,9,8,7,6,5,4,3,2,1,0},
  {0,1,2,11,5,12,6,13,3,9,7,14,4,10,8,15},
  {15,14,11,0,10,1,7,2,12,5,8,3,13,6,9,4},
};

// ---------------- launch ------------------------------------------------------
extern "C" void kernel_launch(void* const* d_in, const int* in_sizes, int n_in,
                              void* d_out, int out_size) {
    const int* map = MAPS[0];
    for (int h = 0; h < 6; h++) {
        bool ok = (n_in >= 16);
        for (int i = 0; ok && i < 16; i++) ok = (in_sizes[i] == SIGS[h][i]);
        if (ok) { map = MAPS[h]; break; }
    }
    const float* x      = (const float*)d_in[map[0]];
    const int*   ei     = (const int*)  d_in[map[1]];
    const float* enc_W1 = (const float*)d_in[map[2]];
    const float* enc_b1 = (const float*)d_in[map[3]];
    const float* enc_W2 = (const float*)d_in[map[4]];
    const float* enc_b2 = (const float*)d_in[map[5]];
    const float* d1_W1  = (const float*)d_in[map[6]];
    const float* d1_b1  = (const float*)d_in[map[7]];
    const float* d1_W2  = (const float*)d_in[map[8]];
    const float* d1_b2  = (const float*)d_in[map[9]];
    const float* d2_W1  = (const float*)d_in[map[10]];
    const float* d2_b1  = (const float*)d_in[map[11]];
    const float* d2_W2  = (const float*)d_in[map[12]];
    const float* d2_b2  = (const float*)d_in[map[13]];
    const float* s_W    = (const float*)d_in[map[14]];
    const float* s_b    = (const float*)d_in[map[15]];
    float* out = (float*)d_out;

    float* o_zs   = out;
    float* o_zns  = out + (size_t)NN * 32;
    float* o_xs   = out + (size_t)NN * 64;
    float* o_xns  = o_xs + (size_t)NN * 256;
    float* o_xscf = o_xns + (size_t)NN * 256;
    float* o_s    = o_xscf + (size_t)NN * 256;   // [N,N] written LAST

    const size_t CH = (size_t)NN * 64;
    float* sc_y1   = o_s + 0 * CH;
    float* sc_A1   = o_s + 1 * CH;
    float* sc_h1   = o_s + 2 * CH;
    float* sc_h1cf = o_s + 3 * CH;
    float* sc_B    = o_s + 4 * CH;
    float* sc_Bcf  = o_s + 5 * CH;
    float* sc_z    = o_s + 6 * CH;
    float* sc_zcf  = o_s + 7 * CH;
    float* sc_t1   = o_s + 8 * CH;
    float* sc_t2   = o_s + 9 * CH;
    float* sc_t3   = o_s + 10 * CH;
    float* sc_at1  = o_s + 11 * CH;
    float* sc_at2  = o_s + 12 * CH;
    float* sc_at3  = o_s + 13 * CH;
    float* sc_az   = o_s + 14 * CH;
    float* sc_az2  = o_s + 14 * CH + (size_t)NN * 32;
    float* sc_azcf = o_s + 14 * CH + (size_t)NN * 64;

    const int TB = 256;
    const int gN   = (NN + TB - 1) / TB;
    const int gE   = (EE + TB - 1) / TB;
    const int gN32 = (NN * 32 + TB - 1) / TB;
    const int gN64 = (NN * 64 + TB - 1) / TB;
    const int gN16 = (NN * 16 + TB - 1) / TB;

    cudaFuncSetAttribute(k_syrk_mma, cudaFuncAttributeMaxDynamicSharedMemorySize,
                         4 * TBYTES);

    // CSR build
    k_zero_deg<<<gN, TB>>>();
    k_count<<<gE, TB>>>(ei);
    k_dinv<<<gN, TB>>>();
    k_scan<<<1, 1024>>>();
    k_scatter<<<gE, TB>>>(ei);

    // encoder conv1
    k_gemm4<INDIM, 64, false><<<gN16, TB>>>(x, enc_W1, nullptr, sc_y1);
    k_cvec<<<gN, TB>>>(x);
    k_agg64c<<<gN32, TB>>>(sc_y1, sc_A1);
    k_h1<<<gN64, TB>>>(sc_A1, enc_W1, enc_b1, sc_h1, sc_h1cf);

    // encoder conv2
    k_agg64x2<<<gN32, TB>>>(sc_h1, sc_h1cf, sc_B, sc_Bcf);
    k_gemm4<64, 64, false><<<gN16, TB>>>(sc_B, enc_W2, enc_b2, sc_z);
    k_gemm4<64, 64, false><<<gN16, TB>>>(sc_Bcf, enc_W2, enc_b2, sc_zcf);
    k_split<<<gN32, TB>>>(sc_z, o_zs, o_zns);

    // fused aggregation of z_s / z_ns / z_s_cf
    k_agg96<<<gN32, TB>>>(sc_z, sc_zcf, sc_az, sc_az2, sc_azcf);

    // decoder first layers + hs (one launch; v==3 writes bf16 hi/lo in-device)
    dim3 dg1(gN16, 4);
    k_dec1<<<dg1, TB>>>(sc_az, sc_az2, sc_azcf, d1_W1, d1_b1, d2_W1, d2_b1,
                        s_W, s_b, sc_t1, sc_t2, sc_t3);

    // fused triple aggregation of decoder hidden states
    k_agg64x3<<<gN32, TB>>>(sc_t1, sc_t2, sc_t3, sc_at1, sc_at2, sc_at3);

    // decoder output layers (one launch, 3 variants)
    dim3 dog(gN64, 3);
    k_decout<<<dog, TB>>>(sc_at1, sc_at2, sc_at3, d1_W2, d2_W2, d1_b2, d2_b2,
                          o_xs, o_xns, o_xscf);

    // tensor-core SYRK via mma.sync
    dim3 syrk_grid(NN / 128, NN / 128);
    k_syrk_mma<<<syrk_grid, 256, 4 * TBYTES>>>(o_s);
}